// round 14
// baseline (speedup 1.0000x reference)
#include <cuda_runtime.h>
#include <cuda_fp16.h>
#include <cstdint>

// VQ-VAE bottleneck — 2-pass split-fp16 HMMA distance GEMM + exact rescore.
// Round 14 = round 13 (passed, 141us) with per-CTA fixed costs amortized:
//   - THREADS 512 / P_CTA 256 / grid 512: half the B copies, half the
//     prologue instances; same 16 warps/SM, same 128 regs, same per-warp
//     mainloop (16 rows x 512 cols).
//   - B copy via cp.async.cg (overlaps A-fill instead of serializing).
//   - qsm winner staging overlays dead B+A smem.
// Numerics identical to r13 (validated r2-r13): fp16 2-pass (a1e1+a2e1),
// scaled operands, per-row margin 4*sqrt(Z)*em + 5e-5; flagged rows rescore
// all 512 k bit-exactly: d = RN(RN(Z+B_k) - 2*seqFMA(z,e_k)), (d,k)-lex min.
// Output: straight-through RN(x + RN(q-x)); loss = RN(L + RN(0.25L)), L = SSE/N.

#define CDIM    64
#define KCODES  512
#define HW      4096
#define NELEM   8388608
#define THREADS 512
#define P_CTA   256
#define GRIDSZ  512
#define QPITCH  65

typedef unsigned long long u64;
typedef unsigned int u32;
typedef unsigned short u16;

__device__ float g_loss_sum;
__device__ u32   g_done;
__device__ float g_cbT[CDIM * KCODES];    // transposed codebook [c][k]
__device__ float g_e2[KCODES];            // ||e_k||^2, reference rounding
__device__ u32   g_em2;                   // bits of max_k ||e_k - fp16(e_k)||^2
__device__ uint4 g_cbB1[4096];            // 64KB fp16(1024*e), SW128 smem layout

// smem layout (bytes); tiles use SW128 swizzle on 128B rows
#define OFF_B1   0          // 512 x 128B fp16 e tile
#define OFF_A(h) (65536 + (h) * 32768)   // 2 x 256 x 128B (fp16 hi/lo of -32z)
#define OFF_E2   131072     // 512 f32
#define OFF_ZS   133120     // 256 f32
#define OFF_KB   134144     // 256 u32
#define OFF_FL   135168     // 256 u32
#define SMEM_SZ  136192
// qsm (winner staging) overlays [0, 66560): B + head of A0, both dead by then

#define SW(o) ((o) ^ (((o) >> 3) & 0x70))

__device__ __forceinline__ u32 smem_u32(const void* p) {
    u32 a; asm("{ .reg .u64 t; cvta.to.shared.u64 t, %1; cvt.u32.u64 %0, t; }" : "=r"(a) : "l"(p));
    return a;
}
__device__ __forceinline__ void cp_async16(u32 dst, const void* src) {
    asm volatile("cp.async.cg.shared.global [%0], [%1], 16;"
                 :: "r"(dst), "l"(src) : "memory");
}
__device__ __forceinline__ void ldsm4(u32 addr, u32& r0, u32& r1, u32& r2, u32& r3) {
    asm volatile("ldmatrix.sync.aligned.m8n8.x4.shared.b16 {%0,%1,%2,%3}, [%4];"
                 : "=r"(r0), "=r"(r1), "=r"(r2), "=r"(r3) : "r"(addr));
}
__device__ __forceinline__ void mma_f16(float* d, const u32* a, u32 b0, u32 b1) {
    asm volatile("mma.sync.aligned.m16n8k16.row.col.f32.f16.f16.f32 "
                 "{%0,%1,%2,%3}, {%4,%5,%6,%7}, {%8,%9}, {%0,%1,%2,%3};"
                 : "+f"(d[0]), "+f"(d[1]), "+f"(d[2]), "+f"(d[3])
                 : "r"(a[0]), "r"(a[1]), "r"(a[2]), "r"(a[3]), "r"(b0), "r"(b1));
}
__device__ __forceinline__ float embed(float s, int k) {
    return __uint_as_float((__float_as_uint(s) & ~511u) | (u32)k);
}
__device__ __forceinline__ void upd2(float& m1, float& m2, float v) {
    float hi = fmaxf(m1, v);
    m1 = fminf(m1, v);
    m2 = fminf(m2, hi);
}

// ---- prep: codebook-derived tables (idempotent across graph replays) ----
__global__ void vq_prep_kernel(const float* __restrict__ cb) {
    int i = blockIdx.x * blockDim.x + threadIdx.x;     // 0..32767
    int k = i >> 6, c = i & 63;
    float e = cb[i];                                    // coalesced
    g_cbT[c * KCODES + k] = e;                          // bit-exact transpose
    __half e1 = __float2half_rn(e * 1024.0f);           // scaled: all normal
    u32 o = SW((u32)(k * 128 + c * 2)) >> 1;            // u16 index, smem layout
    ((u16*)g_cbB1)[o] = *(u16*)&e1;
    if (i < KCODES) {                                   // ||e_i||^2 ref order + residual
        const float* ek = cb + i * CDIM;
        float s = 0.0f, r2 = 0.0f;
        #pragma unroll
        for (int cc = 0; cc < CDIM; cc++) {
            float ev = ek[cc];
            s = __fadd_rn(s, __fmul_rn(ev, ev));
            float eh = __half2float(__float2half_rn(ev * 1024.0f)) * 0.0009765625f;
            float r  = ev - eh;
            r2 += r * r;
        }
        g_e2[i] = s;
        atomicMax(&g_em2, __float_as_uint(r2));         // r2 >= 0: bits monotone
    }
}

extern __shared__ char smc[];

__global__ __launch_bounds__(THREADS, 1)
void vq_main_kernel(const float* __restrict__ x,
                    const float* __restrict__ cb,
                    float* __restrict__ out,
                    int loss_idx) {
    const u32 sb   = smem_u32(smc);
    const int tid  = threadIdx.x;
    const int w    = tid >> 5;
    const int lane = tid & 31;

    float* e2s = (float*)(smc + OFF_E2);
    float* Zs  = (float*)(smc + OFF_ZS);
    u32*   kbs = (u32*)(smc + OFF_KB);
    u32*   fls = (u32*)(smc + OFF_FL);
    float* qsm = (float*)smc;                // overlays B+A0, valid after mainloop

    const int b   = blockIdx.x >> 4;                 // 16 tiles per image
    const int hw0 = (blockIdx.x & 15) * P_CTA;
    const float* xrow = x + (size_t)b * CDIM * HW + hw0;

    // ---- B tile: async 64KB pre-swizzled copy (overlaps A fill) ----
    #pragma unroll
    for (int i = tid; i < 4096; i += THREADS)
        cp_async16(sb + OFF_B1 + i * 16, g_cbB1 + i);
    asm volatile("cp.async.commit_group;" ::: "memory");

    // ---- A tiles: a = -32z (16x scale) split to fp16 hi/lo, SW128 rows ----
    for (int idx = tid; idx < CDIM * P_CTA; idx += THREADS) {
        int c = idx >> 8, p = idx & 255;
        float v = xrow[(size_t)c * HW + p];
        float a = -32.0f * v;                                 // exact
        __half a1 = __float2half_rn(a);
        __half a2 = __float2half_rn(__fadd_rn(a, -__half2float(a1)));
        u32 o = SW((u32)(p * 128 + c * 2));
        *(__half*)(smc + OFF_A(0) + o) = a1;
        *(__half*)(smc + OFF_A(1) + o) = a2;
    }
    // ---- tables; Z per row (ref order) ----
    for (int k = tid; k < KCODES; k += THREADS) e2s[k] = g_e2[k];
    if (tid < P_CTA) {
        float s = 0.0f;
        #pragma unroll
        for (int c = 0; c < CDIM; c++) {
            float zv = xrow[(size_t)c * HW + tid];
            s = __fadd_rn(s, __fmul_rn(zv, zv));
        }
        Zs[tid] = s;
    }
    asm volatile("cp.async.wait_group 0;" ::: "memory");
    __syncthreads();

    // ---- A fragments: 2 halves x 4 k-steps ----
    const int m_base = w * 16;
    const int g      = lane >> 2;
    const int t4     = lane & 3;
    u32 afr[2][4][4];
    {
        int a_r = lane & 15, a_c8 = (lane >> 4) << 3;
        u32 xm  = (u32)((a_r & 7) << 4);
        #pragma unroll
        for (int h = 0; h < 2; h++) {
            u32 lin = sb + OFF_A(h) + (u32)((m_base + a_r) * 128 + a_c8 * 2);
            #pragma unroll
            for (int ks = 0; ks < 4; ks++)
                ldsm4((lin + ks * 32) ^ xm,
                      afr[h][ks][0], afr[h][ks][1], afr[h][ks][2], afr[h][ks][3]);
        }
    }

    const int b_r = (lane & 7) + ((lane >> 4) << 3);
    const int b_c = ((lane >> 3) & 1) << 3;
    const u32 bxm  = (u32)((b_r & 7) << 4);
    const u32 blin = sb + OFF_B1 + (u32)(b_r * 128 + b_c * 2);

    float mA1 = 1e30f, mA2 = 1e30f;      // row m_base+g   (embedded s values)
    float mB1 = 1e30f, mB2 = 1e30f;      // row m_base+g+8
    const float UNSC = 0.00006103515625f;    // 2^-14 (a*16, e*1024)

    #pragma unroll 1
    for (int nc = 0; nc < 16; nc++) {    // 32 codewords per chunk
        float acc[4][4];
        #pragma unroll
        for (int i = 0; i < 4; i++)
            #pragma unroll
            for (int j = 0; j < 4; j++) acc[i][j] = 0.0f;

        #pragma unroll
        for (int ks = 0; ks < 4; ks++) {
            #pragma unroll
            for (int pr = 0; pr < 2; pr++) {
                u32 off = (u32)(nc * 4096 + pr * 2048 + ks * 32);
                u32 c0, c1, c2, c3;
                ldsm4((blin + off) ^ bxm, c0, c1, c2, c3);
                mma_f16(acc[2 * pr],     afr[0][ks], c0, c1);   // a1.e1
                mma_f16(acc[2 * pr],     afr[1][ks], c0, c1);   // a2.e1
                mma_f16(acc[2 * pr + 1], afr[0][ks], c2, c3);
                mma_f16(acc[2 * pr + 1], afr[1][ks], c2, c3);
            }
        }
        #pragma unroll
        for (int nt = 0; nt < 4; nt++) {
            int col0 = nc * 32 + nt * 8 + 2 * t4;
            float e20 = e2s[col0], e21 = e2s[col0 + 1];
            upd2(mA1, mA2, embed(__fmaf_rn(acc[nt][0], UNSC, e20), col0));
            upd2(mA1, mA2, embed(__fmaf_rn(acc[nt][1], UNSC, e21), col0 + 1));
            upd2(mB1, mB2, embed(__fmaf_rn(acc[nt][2], UNSC, e20), col0));
            upd2(mB1, mB2, embed(__fmaf_rn(acc[nt][3], UNSC, e21), col0 + 1));
        }
    }

    // quad reduce (lanes share a row across t4)
    #pragma unroll
    for (int o = 1; o <= 2; o <<= 1) {
        float a1 = __shfl_xor_sync(0xffffffffu, mA1, o);
        float a2 = __shfl_xor_sync(0xffffffffu, mA2, o);
        float hA = fmaxf(mA1, a1);
        mA1 = fminf(mA1, a1);
        mA2 = fminf(fminf(mA2, a2), hA);
        float b1 = __shfl_xor_sync(0xffffffffu, mB1, o);
        float b2 = __shfl_xor_sync(0xffffffffu, mB2, o);
        float hB = fmaxf(mB1, b1);
        mB1 = fminf(mB1, b1);
        mB2 = fminf(fminf(mB2, b2), hB);
    }
    if (t4 == 0) {
        float em = __fsqrt_rn(__uint_as_float(g_em2));
        int r0 = m_base + g, r1 = m_base + g + 8;
        float mg0 = __fmaf_rn(4.0f * __fsqrt_rn(Zs[r0]), em, 5e-5f);
        float mg1 = __fmaf_rn(4.0f * __fsqrt_rn(Zs[r1]), em, 5e-5f);
        kbs[r0] = __float_as_uint(mA1) & 511u;
        kbs[r1] = __float_as_uint(mB1) & 511u;
        fls[r0] = (mA2 - mA1) < mg0;
        fls[r1] = (mB2 - mB1) < mg1;
    }
    __syncwarp();

    // ---- exact rescore of flagged rows: coalesced via g_cbT[c][k] ----
    for (int r = 0; r < 16; r++) {
        int row = m_base + r;
        if (!fls[row]) continue;
        const float* xz = xrow + row;
        float Zp = Zs[row];
        u64 best = ~0ull;
        #pragma unroll 1
        for (int jj = 0; jj < 4; jj++) {
            int k0 = lane + 128 * jj;                 // + 0,32,64,96 below
            float m0 = 0.f, m1 = 0.f, m2 = 0.f, m3 = 0.f;
            #pragma unroll
            for (int c = 0; c < CDIM; c++) {          // c ascending per chain
                float zc = __ldg(xz + (size_t)c * HW);
                const float* ct = g_cbT + c * KCODES + k0;
                m0 = __fmaf_rn(zc, __ldg(ct),      m0);   // lanes consecutive k
                m1 = __fmaf_rn(zc, __ldg(ct + 32), m1);
                m2 = __fmaf_rn(zc, __ldg(ct + 64), m2);
                m3 = __fmaf_rn(zc, __ldg(ct + 96), m3);
            }
            float mm[4] = { m0, m1, m2, m3 };
            #pragma unroll
            for (int i = 0; i < 4; i++) {
                int k = k0 + 32 * i;
                float tt = __fadd_rn(Zp, e2s[k]);
                float d  = __fadd_rn(tt, -2.0f * mm[i]);
                u64 key = ((u64)__float_as_uint(d) << 32) | (u32)k;   // d > 0
                if (key < best) best = key;
            }
        }
        #pragma unroll
        for (int o = 16; o; o >>= 1) {
            u64 v = __shfl_xor_sync(0xffffffffu, best, o);
            if (v < best) best = v;
        }
        if (lane == 0) kbs[row] = (u32)(best & 0x1FFu);
    }
    __syncthreads();   // kbs final; B+A tiles dead -> qsm may overwrite

    // ---- stage winning codewords into smem, coalesced ----
    for (int i = 0; i < 16; i++) {
        int row = m_base + i;
        const float* src = cb + (size_t)kbs[row] * CDIM;
        qsm[row * QPITCH + lane]      = __ldg(src + lane);
        qsm[row * QPITCH + lane + 32] = __ldg(src + lane + 32);
    }
    __syncthreads();

    // ---- writeback: straight-through RN(x + RN(q-x)) + SSE, q from smem ----
    {
        int p = tid & 255, ch = tid >> 8;
        float* op = out + (size_t)b * CDIM * HW + hw0 + p;
        const float* ip = xrow + p;
        const float* qp = qsm + p * QPITCH;
        float sse = 0.0f;
        #pragma unroll 8
        for (int c = ch * 32; c < ch * 32 + 32; c++) {
            float zv   = __ldg(ip + (size_t)c * HW);
            float qv   = qp[c];                        // LDS, conflict-free
            float diff = __fadd_rn(qv, -zv);
            op[(size_t)c * HW] = __fadd_rn(zv, diff);
            sse = __fadd_rn(sse, __fmul_rn(diff, diff));
        }
        #pragma unroll
        for (int o = 16; o; o >>= 1) sse += __shfl_xor_sync(0xffffffffu, sse, o);
        if (lane == 0) atomicAdd(&g_loss_sum, sse);
    }

    // ---- fused finalize, reset for next graph replay ----
    __syncthreads();
    if (tid == 0) {
        __threadfence();
        u32 done = atomicAdd(&g_done, 1u);
        if (done == gridDim.x - 1) {
            float L = atomicAdd(&g_loss_sum, 0.0f) * (1.0f / (float)NELEM);
            if (loss_idx >= 0)
                out[loss_idx] = __fadd_rn(L, 0.25f * L);
            g_loss_sum = 0.0f;
            g_done     = 0u;
            __threadfence();
        }
    }
}

extern "C" void kernel_launch(void* const* d_in, const int* in_sizes, int n_in,
                              void* d_out, int out_size) {
    const float* x   = (const float*)d_in[0];
    const float* cb  = (const float*)d_in[1];
    float*       out = (float*)d_out;

    cudaFuncSetAttribute(vq_main_kernel,
                         cudaFuncAttributeMaxDynamicSharedMemorySize, SMEM_SZ);
    int loss_idx = (out_size > NELEM) ? (out_size - 1) : -1;
    vq_prep_kernel<<<128, 256>>>(cb);
    vq_main_kernel<<<GRIDSZ, THREADS, SMEM_SZ>>>(x, cb, out, loss_idx);
}

// round 15
// speedup vs baseline: 1.0518x; 1.0518x over previous
#include <cuda_runtime.h>
#include <cuda_fp16.h>
#include <cstdint>

// VQ-VAE bottleneck — 2-pass split-fp16 HMMA distance GEMM + exact rescore,
// persistent work-stealing CTAs.
// Round 15 = round 13 (passed, 141us; 256 thr / 2 CTAs/SM) with:
//   - grid 304 persistent CTAs, tiles (1024 x 128 positions) fetched from a
//     global atomic counter: kills the 4-wave quantization (~13% idle) and
//     smooths rescore-straggler tiles; B tile + copy amortized over ~3.4 tiles.
//   - qsm winner staging overlays the dead A tiles (B must persist); e2s
//     (partially clobbered by qsm) reloaded per tile.
// Numerics identical to r13 (validated r2-r14): fp16 2-pass (a1e1+a2e1),
// scaled operands, per-row margin 4*sqrt(Z)*em + 5e-5; flagged rows rescore
// all 512 k bit-exactly: d = RN(RN(Z+B_k) - 2*seqFMA(z,e_k)), (d,k)-lex min.
// Output: straight-through RN(x + RN(q-x)); loss = RN(L + RN(0.25L)), L = SSE/N.

#define CDIM    64
#define KCODES  512
#define HW      4096
#define NELEM   8388608
#define THREADS 256
#define P_CTA   128
#define NTILES  1024
#define GRIDSZ  304
#define QPITCH  65

typedef unsigned long long u64;
typedef unsigned int u32;
typedef unsigned short u16;

__device__ float g_loss_sum;
__device__ u32   g_done;
__device__ u32   g_tile;                  // persistent work counter
__device__ float g_cbT[CDIM * KCODES];    // transposed codebook [c][k]
__device__ float g_e2[KCODES];            // ||e_k||^2, reference rounding
__device__ u32   g_em2;                   // bits of max_k ||e_k - fp16(e_k)||^2
__device__ uint4 g_cbB1[4096];            // 64KB fp16(1024*e), SW128 smem layout

// smem layout (bytes); tiles use SW128 swizzle on 128B rows
#define OFF_B1   0          // 512 x 128B fp16 e tile (persists across tiles)
#define OFF_A(h) (65536 + (h) * 16384)   // 2 x 128 x 128B (fp16 hi/lo of -32z)
#define OFF_E2   98304      // 512 f32   (head clobbered by qsm; reload per tile)
#define OFF_ZS   100352     // 128 f32
#define OFF_KB   100864     // 128 u32
#define OFF_FL   101376     // 128 u32
#define OFF_TS   101888     // 1 u32 current tile
#define SMEM_SZ  102400
// qsm staging = smc + OFF_A(0), 33280B: overlays A0+A1+e2s[0..128) (all dead)

#define SW(o) ((o) ^ (((o) >> 3) & 0x70))

__device__ __forceinline__ u32 smem_u32(const void* p) {
    u32 a; asm("{ .reg .u64 t; cvta.to.shared.u64 t, %1; cvt.u32.u64 %0, t; }" : "=r"(a) : "l"(p));
    return a;
}
__device__ __forceinline__ void ldsm4(u32 addr, u32& r0, u32& r1, u32& r2, u32& r3) {
    asm volatile("ldmatrix.sync.aligned.m8n8.x4.shared.b16 {%0,%1,%2,%3}, [%4];"
                 : "=r"(r0), "=r"(r1), "=r"(r2), "=r"(r3) : "r"(addr));
}
__device__ __forceinline__ void mma_f16(float* d, const u32* a, u32 b0, u32 b1) {
    asm volatile("mma.sync.aligned.m16n8k16.row.col.f32.f16.f16.f32 "
                 "{%0,%1,%2,%3}, {%4,%5,%6,%7}, {%8,%9}, {%0,%1,%2,%3};"
                 : "+f"(d[0]), "+f"(d[1]), "+f"(d[2]), "+f"(d[3])
                 : "r"(a[0]), "r"(a[1]), "r"(a[2]), "r"(a[3]), "r"(b0), "r"(b1));
}
__device__ __forceinline__ float embed(float s, int k) {
    return __uint_as_float((__float_as_uint(s) & ~511u) | (u32)k);
}
__device__ __forceinline__ void upd2(float& m1, float& m2, float v) {
    float hi = fmaxf(m1, v);
    m1 = fminf(m1, v);
    m2 = fminf(m2, hi);
}

// ---- prep: codebook-derived tables (idempotent across graph replays) ----
__global__ void vq_prep_kernel(const float* __restrict__ cb) {
    int i = blockIdx.x * blockDim.x + threadIdx.x;     // 0..32767
    int k = i >> 6, c = i & 63;
    float e = cb[i];                                    // coalesced
    g_cbT[c * KCODES + k] = e;                          // bit-exact transpose
    __half e1 = __float2half_rn(e * 1024.0f);           // scaled: all normal
    u32 o = SW((u32)(k * 128 + c * 2)) >> 1;            // u16 index, smem layout
    ((u16*)g_cbB1)[o] = *(u16*)&e1;
    if (i < KCODES) {                                   // ||e_i||^2 ref order + residual
        const float* ek = cb + i * CDIM;
        float s = 0.0f, r2 = 0.0f;
        #pragma unroll
        for (int cc = 0; cc < CDIM; cc++) {
            float ev = ek[cc];
            s = __fadd_rn(s, __fmul_rn(ev, ev));
            float eh = __half2float(__float2half_rn(ev * 1024.0f)) * 0.0009765625f;
            float r  = ev - eh;
            r2 += r * r;
        }
        g_e2[i] = s;
        atomicMax(&g_em2, __float_as_uint(r2));         // r2 >= 0: bits monotone
    }
}

extern __shared__ char smc[];

__global__ __launch_bounds__(THREADS, 2)
void vq_main_kernel(const float* __restrict__ x,
                    const float* __restrict__ cb,
                    float* __restrict__ out,
                    int loss_idx) {
    const u32 sb   = smem_u32(smc);
    const int tid  = threadIdx.x;
    const int w    = tid >> 5;
    const int lane = tid & 31;

    float* e2s = (float*)(smc + OFF_E2);
    float* Zs  = (float*)(smc + OFF_ZS);
    u32*   kbs = (u32*)(smc + OFF_KB);
    u32*   fls = (u32*)(smc + OFF_FL);
    u32*   tsm = (u32*)(smc + OFF_TS);
    float* qsm = (float*)(smc + OFF_A(0));   // staging overlay, post-mainloop

    // ---- B tile: one 64KB pre-swizzled copy per CTA (persists) ----
    {
        const uint4* s1 = g_cbB1;
        uint4* d1 = (uint4*)(smc + OFF_B1);
        #pragma unroll
        for (int i = tid; i < 4096; i += THREADS) d1[i] = s1[i];
    }

    const int m_base = w * 16;
    const int g      = lane >> 2;
    const int t4     = lane & 3;
    const int b_r    = (lane & 7) + ((lane >> 4) << 3);
    const int b_c    = ((lane >> 3) & 1) << 3;
    const u32 bxm    = (u32)((b_r & 7) << 4);
    const u32 blin   = sb + OFF_B1 + (u32)(b_r * 128 + b_c * 2);
    const float UNSC = 0.00006103515625f;    // 2^-14 (a*16, e*1024)

    // ================= persistent tile loop =================
    for (;;) {
        if (tid == 0) *tsm = atomicAdd(&g_tile, 1u);
        __syncthreads();                      // also guards prior-tile smem reuse
        int tile = (int)*tsm;
        if (tile >= NTILES) break;

        const int b   = tile >> 5;
        const int hw0 = (tile & 31) * P_CTA;
        const float* xrow = x + (size_t)b * CDIM * HW + hw0;

        // ---- A tiles: a = -32z split to fp16 hi/lo, SW128 rows ----
        for (int idx = tid; idx < CDIM * P_CTA; idx += THREADS) {
            int c = idx >> 7, p = idx & 127;
            float v = xrow[(size_t)c * HW + p];
            float a = -32.0f * v;                                 // exact
            __half a1 = __float2half_rn(a);
            __half a2 = __float2half_rn(__fadd_rn(a, -__half2float(a1)));
            u32 o = SW((u32)(p * 128 + c * 2));
            *(__half*)(smc + OFF_A(0) + o) = a1;
            *(__half*)(smc + OFF_A(1) + o) = a2;
        }
        // ---- e2s reload (head clobbered by qsm last tile); Z per row ----
        for (int k = tid; k < KCODES; k += THREADS) e2s[k] = g_e2[k];
        if (tid < P_CTA) {
            float s = 0.0f;
            #pragma unroll
            for (int c = 0; c < CDIM; c++) {
                float zv = xrow[(size_t)c * HW + tid];
                s = __fadd_rn(s, __fmul_rn(zv, zv));
            }
            Zs[tid] = s;
        }
        __syncthreads();

        // ---- A fragments: 2 halves x 4 k-steps ----
        u32 afr[2][4][4];
        {
            int a_r = lane & 15, a_c8 = (lane >> 4) << 3;
            u32 xm  = (u32)((a_r & 7) << 4);
            #pragma unroll
            for (int h = 0; h < 2; h++) {
                u32 lin = sb + OFF_A(h) + (u32)((m_base + a_r) * 128 + a_c8 * 2);
                #pragma unroll
                for (int ks = 0; ks < 4; ks++)
                    ldsm4((lin + ks * 32) ^ xm,
                          afr[h][ks][0], afr[h][ks][1], afr[h][ks][2], afr[h][ks][3]);
            }
        }

        float mA1 = 1e30f, mA2 = 1e30f;      // row m_base+g   (embedded s)
        float mB1 = 1e30f, mB2 = 1e30f;      // row m_base+g+8

        #pragma unroll 1
        for (int nc = 0; nc < 16; nc++) {    // 32 codewords per chunk
            float acc[4][4];
            #pragma unroll
            for (int i = 0; i < 4; i++)
                #pragma unroll
                for (int j = 0; j < 4; j++) acc[i][j] = 0.0f;

            #pragma unroll
            for (int ks = 0; ks < 4; ks++) {
                #pragma unroll
                for (int pr = 0; pr < 2; pr++) {
                    u32 off = (u32)(nc * 4096 + pr * 2048 + ks * 32);
                    u32 c0, c1, c2, c3;
                    ldsm4((blin + off) ^ bxm, c0, c1, c2, c3);
                    mma_f16(acc[2 * pr],     afr[0][ks], c0, c1);   // a1.e1
                    mma_f16(acc[2 * pr],     afr[1][ks], c0, c1);   // a2.e1
                    mma_f16(acc[2 * pr + 1], afr[0][ks], c2, c3);
                    mma_f16(acc[2 * pr + 1], afr[1][ks], c2, c3);
                }
            }
            #pragma unroll
            for (int nt = 0; nt < 4; nt++) {
                int col0 = nc * 32 + nt * 8 + 2 * t4;
                float e20 = e2s[col0], e21 = e2s[col0 + 1];
                upd2(mA1, mA2, embed(__fmaf_rn(acc[nt][0], UNSC, e20), col0));
                upd2(mA1, mA2, embed(__fmaf_rn(acc[nt][1], UNSC, e21), col0 + 1));
                upd2(mB1, mB2, embed(__fmaf_rn(acc[nt][2], UNSC, e20), col0));
                upd2(mB1, mB2, embed(__fmaf_rn(acc[nt][3], UNSC, e21), col0 + 1));
            }
        }

        // quad reduce (lanes share a row across t4)
        #pragma unroll
        for (int o = 1; o <= 2; o <<= 1) {
            float a1 = __shfl_xor_sync(0xffffffffu, mA1, o);
            float a2 = __shfl_xor_sync(0xffffffffu, mA2, o);
            float hA = fmaxf(mA1, a1);
            mA1 = fminf(mA1, a1);
            mA2 = fminf(fminf(mA2, a2), hA);
            float b1 = __shfl_xor_sync(0xffffffffu, mB1, o);
            float b2 = __shfl_xor_sync(0xffffffffu, mB2, o);
            float hB = fmaxf(mB1, b1);
            mB1 = fminf(mB1, b1);
            mB2 = fminf(fminf(mB2, b2), hB);
        }
        if (t4 == 0) {
            float em = __fsqrt_rn(__uint_as_float(g_em2));
            int r0 = m_base + g, r1 = m_base + g + 8;
            float mg0 = __fmaf_rn(4.0f * __fsqrt_rn(Zs[r0]), em, 5e-5f);
            float mg1 = __fmaf_rn(4.0f * __fsqrt_rn(Zs[r1]), em, 5e-5f);
            kbs[r0] = __float_as_uint(mA1) & 511u;
            kbs[r1] = __float_as_uint(mB1) & 511u;
            fls[r0] = (mA2 - mA1) < mg0;
            fls[r1] = (mB2 - mB1) < mg1;
        }
        __syncwarp();

        // ---- exact rescore of flagged rows: coalesced via g_cbT[c][k] ----
        for (int r = 0; r < 16; r++) {
            int row = m_base + r;
            if (!fls[row]) continue;
            const float* xz = xrow + row;
            float Zp = Zs[row];
            u64 best = ~0ull;
            #pragma unroll 1
            for (int jj = 0; jj < 4; jj++) {
                int k0 = lane + 128 * jj;                 // + 0,32,64,96 below
                float m0 = 0.f, m1 = 0.f, m2 = 0.f, m3 = 0.f;
                #pragma unroll
                for (int c = 0; c < CDIM; c++) {          // c ascending per chain
                    float zc = __ldg(xz + (size_t)c * HW);
                    const float* ct = g_cbT + c * KCODES + k0;
                    m0 = __fmaf_rn(zc, __ldg(ct),      m0);   // lanes consecutive k
                    m1 = __fmaf_rn(zc, __ldg(ct + 32), m1);
                    m2 = __fmaf_rn(zc, __ldg(ct + 64), m2);
                    m3 = __fmaf_rn(zc, __ldg(ct + 96), m3);
                }
                float mm[4] = { m0, m1, m2, m3 };
                #pragma unroll
                for (int i = 0; i < 4; i++) {
                    int k = k0 + 32 * i;
                    float tt = __fadd_rn(Zp, e2s[k]);
                    float d  = __fadd_rn(tt, -2.0f * mm[i]);
                    u64 key = ((u64)__float_as_uint(d) << 32) | (u32)k;   // d > 0
                    if (key < best) best = key;
                }
            }
            #pragma unroll
            for (int o = 16; o; o >>= 1) {
                u64 v = __shfl_xor_sync(0xffffffffu, best, o);
                if (v < best) best = v;
            }
            if (lane == 0) kbs[row] = (u32)(best & 0x1FFu);
        }
        __syncthreads();   // kbs final; A tiles dead -> qsm may overwrite

        // ---- stage winning codewords into smem, coalesced ----
        for (int i = 0; i < 16; i++) {
            int row = m_base + i;
            const float* src = cb + (size_t)kbs[row] * CDIM;
            qsm[row * QPITCH + lane]      = __ldg(src + lane);
            qsm[row * QPITCH + lane + 32] = __ldg(src + lane + 32);
        }
        __syncthreads();

        // ---- writeback: straight-through RN(x + RN(q-x)) + SSE ----
        {
            int p = tid & 127, ch = tid >> 7;
            float* op = out + (size_t)b * CDIM * HW + hw0 + p;
            const float* ip = xrow + p;
            const float* qp = qsm + p * QPITCH;
            float sse = 0.0f;
            #pragma unroll 8
            for (int c = ch * 32; c < ch * 32 + 32; c++) {
                float zv   = __ldg(ip + (size_t)c * HW);
                float qv   = qp[c];                        // LDS, conflict-free
                float diff = __fadd_rn(qv, -zv);
                op[(size_t)c * HW] = __fadd_rn(zv, diff);
                sse = __fadd_rn(sse, __fmul_rn(diff, diff));
            }
            #pragma unroll
            for (int o = 16; o; o >>= 1) sse += __shfl_xor_sync(0xffffffffu, sse, o);
            if (lane == 0) atomicAdd(&g_loss_sum, sse);
        }
    }
    // ================= end persistent loop =================

    // ---- fused finalize: last CTA emits loss, resets counters for replay ----
    if (tid == 0) {
        __threadfence();
        u32 done = atomicAdd(&g_done, 1u);
        if (done == gridDim.x - 1) {
            float L = atomicAdd(&g_loss_sum, 0.0f) * (1.0f / (float)NELEM);
            if (loss_idx >= 0)
                out[loss_idx] = __fadd_rn(L, 0.25f * L);
            g_loss_sum = 0.0f;
            g_done     = 0u;
            g_tile     = 0u;
            __threadfence();
        }
    }
}

extern "C" void kernel_launch(void* const* d_in, const int* in_sizes, int n_in,
                              void* d_out, int out_size) {
    const float* x   = (const float*)d_in[0];
    const float* cb  = (const float*)d_in[1];
    float*       out = (float*)d_out;

    cudaFuncSetAttribute(vq_main_kernel,
                         cudaFuncAttributeMaxDynamicSharedMemorySize, SMEM_SZ);
    int loss_idx = (out_size > NELEM) ? (out_size - 1) : -1;
    vq_prep_kernel<<<128, 256>>>(cb);
    vq_main_kernel<<<GRIDSZ, THREADS, SMEM_SZ>>>(x, cb, out, loss_idx);
}

// round 16
// speedup vs baseline: 1.1061x; 1.0517x over previous
#include <cuda_runtime.h>
#include <cuda_fp16.h>
#include <cstdint>

// VQ-VAE bottleneck — 2-pass split-fp16 HMMA distance GEMM + exact rescore.
// Round 16 = round 13 (best, 141us) + two critical-path cuts:
//   (1) fused prologue: threads 0-127 load x ONCE per element (c ascending,
//       reference order), producing both fp16 split halves AND Z; threads
//       128-255 concurrently copy the 64KB pre-swizzled B tile. Halves
//       prologue gmem traffic and overlaps B copy with A fill.
//   (2) mainloop mma reordered for dependency distance 4 (acc0..3 a1, then
//       acc0..3 a2) instead of back-to-back dependent mma.
// Numerics identical to r13 (validated r2-r15): fp16 2-pass (a1e1+a2e1),
// scaled operands, per-row margin 4*sqrt(Z)*em + 5e-5; flagged rows rescore
// all 512 k bit-exactly: d = RN(RN(Z+B_k) - 2*seqFMA(z,e_k)), (d,k)-lex min.
// Output: straight-through RN(x + RN(q-x)); loss = RN(L + RN(0.25L)), L = SSE/N.

#define CDIM    64
#define KCODES  512
#define HW      4096
#define NELEM   8388608
#define THREADS 256
#define P_CTA   128
#define GRIDSZ  1024
#define QPITCH  65

typedef unsigned long long u64;
typedef unsigned int u32;
typedef unsigned short u16;

__device__ float g_loss_sum;
__device__ u32   g_done;
__device__ float g_cbT[CDIM * KCODES];    // transposed codebook [c][k]
__device__ float g_e2[KCODES];            // ||e_k||^2, reference rounding
__device__ u32   g_em2;                   // bits of max_k ||e_k - fp16(e_k)||^2
__device__ uint4 g_cbB1[4096];            // 64KB fp16(1024*e), SW128 smem layout

// smem layout (bytes); tiles use SW128 swizzle on 128B rows
#define OFF_B1   0          // 512 x 128B fp16 e tile; later qsm (33280B fits)
#define OFF_A(h) (65536 + (h) * 16384)   // 2 x 128 x 128B (fp16 hi/lo of -32z)
#define OFF_E2   98304      // 512 f32
#define OFF_ZS   100352     // 128 f32
#define OFF_KB   100864     // 128 u32
#define OFF_FL   101376     // 128 u32
#define SMEM_SZ  101888

#define SW(o) ((o) ^ (((o) >> 3) & 0x70))

__device__ __forceinline__ u32 smem_u32(const void* p) {
    u32 a; asm("{ .reg .u64 t; cvta.to.shared.u64 t, %1; cvt.u32.u64 %0, t; }" : "=r"(a) : "l"(p));
    return a;
}
__device__ __forceinline__ void ldsm4(u32 addr, u32& r0, u32& r1, u32& r2, u32& r3) {
    asm volatile("ldmatrix.sync.aligned.m8n8.x4.shared.b16 {%0,%1,%2,%3}, [%4];"
                 : "=r"(r0), "=r"(r1), "=r"(r2), "=r"(r3) : "r"(addr));
}
__device__ __forceinline__ void mma_f16(float* d, const u32* a, u32 b0, u32 b1) {
    asm volatile("mma.sync.aligned.m16n8k16.row.col.f32.f16.f16.f32 "
                 "{%0,%1,%2,%3}, {%4,%5,%6,%7}, {%8,%9}, {%0,%1,%2,%3};"
                 : "+f"(d[0]), "+f"(d[1]), "+f"(d[2]), "+f"(d[3])
                 : "r"(a[0]), "r"(a[1]), "r"(a[2]), "r"(a[3]), "r"(b0), "r"(b1));
}
__device__ __forceinline__ float embed(float s, int k) {
    return __uint_as_float((__float_as_uint(s) & ~511u) | (u32)k);
}
__device__ __forceinline__ void upd2(float& m1, float& m2, float v) {
    float hi = fmaxf(m1, v);
    m1 = fminf(m1, v);
    m2 = fminf(m2, hi);
}

// ---- prep: codebook-derived tables (idempotent across graph replays) ----
__global__ void vq_prep_kernel(const float* __restrict__ cb) {
    int i = blockIdx.x * blockDim.x + threadIdx.x;     // 0..32767
    int k = i >> 6, c = i & 63;
    float e = cb[i];                                    // coalesced
    g_cbT[c * KCODES + k] = e;                          // bit-exact transpose
    __half e1 = __float2half_rn(e * 1024.0f);           // scaled: all normal
    u32 o = SW((u32)(k * 128 + c * 2)) >> 1;            // u16 index, smem layout
    ((u16*)g_cbB1)[o] = *(u16*)&e1;
    if (i < KCODES) {                                   // ||e_i||^2 ref order + residual
        const float* ek = cb + i * CDIM;
        float s = 0.0f, r2 = 0.0f;
        #pragma unroll
        for (int cc = 0; cc < CDIM; cc++) {
            float ev = ek[cc];
            s = __fadd_rn(s, __fmul_rn(ev, ev));
            float eh = __half2float(__float2half_rn(ev * 1024.0f)) * 0.0009765625f;
            float r  = ev - eh;
            r2 += r * r;
        }
        g_e2[i] = s;
        atomicMax(&g_em2, __float_as_uint(r2));         // r2 >= 0: bits monotone
    }
}

extern __shared__ char smc[];

__global__ __launch_bounds__(THREADS, 2)
void vq_main_kernel(const float* __restrict__ x,
                    const float* __restrict__ cb,
                    float* __restrict__ out,
                    int loss_idx) {
    const u32 sb   = smem_u32(smc);
    const int tid  = threadIdx.x;
    const int w    = tid >> 5;
    const int lane = tid & 31;

    float* e2s = (float*)(smc + OFF_E2);
    float* Zs  = (float*)(smc + OFF_ZS);
    u32*   kbs = (u32*)(smc + OFF_KB);
    u32*   fls = (u32*)(smc + OFF_FL);
    float* qsm = (float*)(smc + OFF_B1);     // valid after mainloop

    const int b   = blockIdx.x >> 5;
    const int hw0 = (blockIdx.x & 31) * P_CTA;
    const float* xrow = x + (size_t)b * CDIM * HW + hw0;

    // ---- fused prologue, warp-specialized ----
    if (tid < P_CTA) {
        // threads 0-127: position p = tid. Single sweep over c (ascending,
        // reference order): load x once -> fp16 split A halves + Z.
        const int p = tid;
        const float* xp = xrow + p;
        float s = 0.0f;
        #pragma unroll 8
        for (int c = 0; c < CDIM; c++) {
            float v = __ldg(xp + (size_t)c * HW);       // coalesced across p
            s = __fadd_rn(s, __fmul_rn(v, v));          // ref-order Z chain
            float a = -32.0f * v;                       // exact
            __half a1 = __float2half_rn(a);
            __half a2 = __float2half_rn(__fadd_rn(a, -__half2float(a1)));
            u32 o = SW((u32)(p * 128 + c * 2));
            *(__half*)(smc + OFF_A(0) + o) = a1;
            *(__half*)(smc + OFF_A(1) + o) = a2;
        }
        Zs[p] = s;
    } else {
        // threads 128-255: 64KB pre-swizzled B copy (32 uint4 each)
        const uint4* s1 = g_cbB1;
        uint4* d1 = (uint4*)(smc + OFF_B1);
        int t = tid - 128;
        #pragma unroll
        for (int i = t; i < 4096; i += 128) d1[i] = s1[i];
    }
    for (int k = tid; k < KCODES; k += THREADS) e2s[k] = g_e2[k];
    __syncthreads();

    // ---- A fragments: 2 halves x 4 k-steps ----
    const int m_base = w * 16;
    const int g      = lane >> 2;
    const int t4     = lane & 3;
    u32 afr[2][4][4];
    {
        int a_r = lane & 15, a_c8 = (lane >> 4) << 3;
        u32 xm  = (u32)((a_r & 7) << 4);
        #pragma unroll
        for (int h = 0; h < 2; h++) {
            u32 lin = sb + OFF_A(h) + (u32)((m_base + a_r) * 128 + a_c8 * 2);
            #pragma unroll
            for (int ks = 0; ks < 4; ks++)
                ldsm4((lin + ks * 32) ^ xm,
                      afr[h][ks][0], afr[h][ks][1], afr[h][ks][2], afr[h][ks][3]);
        }
    }

    const int b_r = (lane & 7) + ((lane >> 4) << 3);
    const int b_c = ((lane >> 3) & 1) << 3;
    const u32 bxm  = (u32)((b_r & 7) << 4);
    const u32 blin = sb + OFF_B1 + (u32)(b_r * 128 + b_c * 2);

    float mA1 = 1e30f, mA2 = 1e30f;      // row m_base+g   (embedded s values)
    float mB1 = 1e30f, mB2 = 1e30f;      // row m_base+g+8
    const float UNSC = 0.00006103515625f;    // 2^-14 (a*16, e*1024)

    #pragma unroll 1
    for (int nc = 0; nc < 16; nc++) {    // 32 codewords per chunk
        float acc[4][4];
        #pragma unroll
        for (int i = 0; i < 4; i++)
            #pragma unroll
            for (int j = 0; j < 4; j++) acc[i][j] = 0.0f;

        #pragma unroll
        for (int ks = 0; ks < 4; ks++) {
            // load BOTH pr blocks first, then issue 8 mma at dependency
            // distance 4 (acc0..3 with a1, then acc0..3 with a2)
            u32 off0 = (u32)(nc * 4096 + ks * 32);
            u32 c0, c1, c2, c3, d0, d1, d2, d3;
            ldsm4((blin + off0) ^ bxm,        c0, c1, c2, c3);
            ldsm4((blin + off0 + 2048) ^ bxm, d0, d1, d2, d3);
            mma_f16(acc[0], afr[0][ks], c0, c1);
            mma_f16(acc[1], afr[0][ks], c2, c3);
            mma_f16(acc[2], afr[0][ks], d0, d1);
            mma_f16(acc[3], afr[0][ks], d2, d3);
            mma_f16(acc[0], afr[1][ks], c0, c1);
            mma_f16(acc[1], afr[1][ks], c2, c3);
            mma_f16(acc[2], afr[1][ks], d0, d1);
            mma_f16(acc[3], afr[1][ks], d2, d3);
        }
        // acc[0],acc[1] = pr0 cols; acc[2],acc[3] = pr1 cols
        #pragma unroll
        for (int pr = 0; pr < 2; pr++) {
            #pragma unroll
            for (int nt = 0; nt < 2; nt++) {
                int col0 = nc * 32 + pr * 16 + nt * 8 + 2 * t4;
                float* a = acc[pr * 2 + nt];
                float e20 = e2s[col0], e21 = e2s[col0 + 1];
                upd2(mA1, mA2, embed(__fmaf_rn(a[0], UNSC, e20), col0));
                upd2(mA1, mA2, embed(__fmaf_rn(a[1], UNSC, e21), col0 + 1));
                upd2(mB1, mB2, embed(__fmaf_rn(a[2], UNSC, e20), col0));
                upd2(mB1, mB2, embed(__fmaf_rn(a[3], UNSC, e21), col0 + 1));
            }
        }
    }

    // quad reduce (lanes share a row across t4)
    #pragma unroll
    for (int o = 1; o <= 2; o <<= 1) {
        float a1 = __shfl_xor_sync(0xffffffffu, mA1, o);
        float a2 = __shfl_xor_sync(0xffffffffu, mA2, o);
        float hA = fmaxf(mA1, a1);
        mA1 = fminf(mA1, a1);
        mA2 = fminf(fminf(mA2, a2), hA);
        float b1 = __shfl_xor_sync(0xffffffffu, mB1, o);
        float b2 = __shfl_xor_sync(0xffffffffu, mB2, o);
        float hB = fmaxf(mB1, b1);
        mB1 = fminf(mB1, b1);
        mB2 = fminf(fminf(mB2, b2), hB);
    }
    if (t4 == 0) {
        float em = __fsqrt_rn(__uint_as_float(g_em2));
        int r0 = m_base + g, r1 = m_base + g + 8;
        float mg0 = __fmaf_rn(4.0f * __fsqrt_rn(Zs[r0]), em, 5e-5f);
        float mg1 = __fmaf_rn(4.0f * __fsqrt_rn(Zs[r1]), em, 5e-5f);
        kbs[r0] = __float_as_uint(mA1) & 511u;
        kbs[r1] = __float_as_uint(mB1) & 511u;
        fls[r0] = (mA2 - mA1) < mg0;
        fls[r1] = (mB2 - mB1) < mg1;
    }
    __syncwarp();

    // ---- exact rescore of flagged rows: coalesced via g_cbT[c][k] ----
    for (int r = 0; r < 16; r++) {
        int row = m_base + r;
        if (!fls[row]) continue;
        const float* xz = xrow + row;
        float Zp = Zs[row];
        u64 best = ~0ull;
        #pragma unroll 1
        for (int jj = 0; jj < 4; jj++) {
            int k0 = lane + 128 * jj;                 // + 0,32,64,96 below
            float m0 = 0.f, m1 = 0.f, m2 = 0.f, m3 = 0.f;
            #pragma unroll
            for (int c = 0; c < CDIM; c++) {          // c ascending per chain
                float zc = __ldg(xz + (size_t)c * HW);
                const float* ct = g_cbT + c * KCODES + k0;
                m0 = __fmaf_rn(zc, __ldg(ct),      m0);   // lanes consecutive k
                m1 = __fmaf_rn(zc, __ldg(ct + 32), m1);
                m2 = __fmaf_rn(zc, __ldg(ct + 64), m2);
                m3 = __fmaf_rn(zc, __ldg(ct + 96), m3);
            }
            float mm[4] = { m0, m1, m2, m3 };
            #pragma unroll
            for (int i = 0; i < 4; i++) {
                int k = k0 + 32 * i;
                float tt = __fadd_rn(Zp, e2s[k]);
                float d  = __fadd_rn(tt, -2.0f * mm[i]);
                u64 key = ((u64)__float_as_uint(d) << 32) | (u32)k;   // d > 0
                if (key < best) best = key;
            }
        }
        #pragma unroll
        for (int o = 16; o; o >>= 1) {
            u64 v = __shfl_xor_sync(0xffffffffu, best, o);
            if (v < best) best = v;
        }
        if (lane == 0) kbs[row] = (u32)(best & 0x1FFu);
    }
    __syncthreads();   // kbs final; B tile dead -> qsm may overwrite

    // ---- stage winning codewords into smem, coalesced ----
    for (int i = 0; i < 16; i++) {
        int row = m_base + i;
        const float* src = cb + (size_t)kbs[row] * CDIM;
        qsm[row * QPITCH + lane]      = __ldg(src + lane);
        qsm[row * QPITCH + lane + 32] = __ldg(src + lane + 32);
    }
    __syncthreads();

    // ---- writeback: straight-through RN(x + RN(q-x)) + SSE, q from smem ----
    {
        int p = tid & 127, ch = tid >> 7;
        float* op = out + (size_t)b * CDIM * HW + hw0 + p;
        const float* ip = xrow + p;
        const float* qp = qsm + p * QPITCH;
        float sse = 0.0f;
        #pragma unroll 8
        for (int c = ch * 32; c < ch * 32 + 32; c++) {
            float zv   = __ldg(ip + (size_t)c * HW);
            float qv   = qp[c];                        // LDS, conflict-free
            float diff = __fadd_rn(qv, -zv);
            op[(size_t)c * HW] = __fadd_rn(zv, diff);
            sse = __fadd_rn(sse, __fmul_rn(diff, diff));
        }
        #pragma unroll
        for (int o = 16; o; o >>= 1) sse += __shfl_xor_sync(0xffffffffu, sse, o);
        if (lane == 0) atomicAdd(&g_loss_sum, sse);
    }

    // ---- fused finalize, reset for next graph replay ----
    __syncthreads();
    if (tid == 0) {
        __threadfence();
        u32 done = atomicAdd(&g_done, 1u);
        if (done == gridDim.x - 1) {
            float L = atomicAdd(&g_loss_sum, 0.0f) * (1.0f / (float)NELEM);
            if (loss_idx >= 0)
                out[loss_idx] = __fadd_rn(L, 0.25f * L);
            g_loss_sum = 0.0f;
            g_done     = 0u;
            __threadfence();
        }
    }
}

extern "C" void kernel_launch(void* const* d_in, const int* in_sizes, int n_in,
                              void* d_out, int out_size) {
    const float* x   = (const float*)d_in[0];
    const float* cb  = (const float*)d_in[1];
    float*       out = (float*)d_out;

    cudaFuncSetAttribute(vq_main_kernel,
                         cudaFuncAttributeMaxDynamicSharedMemorySize, SMEM_SZ);
    int loss_idx = (out_size > NELEM) ? (out_size - 1) : -1;
    vq_prep_kernel<<<128, 256>>>(cb);
    vq_main_kernel<<<GRIDSZ, THREADS, SMEM_SZ>>>(x, cb, out, loss_idx);
}